// round 4
// baseline (speedup 1.0000x reference)
#include <cuda_runtime.h>

// Gated DeltaNet single step:
//   out[v] = g*(q . S[:,v]) + (q . k)*beta*(v[v] - g*(k . S[:,v]))
// One CTA (4 warps) per head; warp w streams rows [32w, 32w+32) (16KB),
// partial qS/kS combined in smem. Fine CTA granularity (64KB/CTA) smooths
// the drain tail that capped DRAM at 81% with 512KB CTAs.

#define DK 128
#define DV 128
#define NWARP 4

__global__ __launch_bounds__(DV)
void deltanet_step_kernel(const float* __restrict__ q,
                          const float* __restrict__ k,
                          const float* __restrict__ v,
                          const float* __restrict__ beta,
                          const float* __restrict__ gate,
                          const float* __restrict__ state,
                          float* __restrict__ out) {
    const int bh   = blockIdx.x;
    const int t    = threadIdx.x;        // 0..127
    const int warp = t >> 5;
    const int lane = t & 31;

    __shared__ float sq[DK];
    __shared__ float sk[DK];
    __shared__ float redQ[NWARP][DV];
    __shared__ float redK[NWARP][DV];
    __shared__ float wqk[NWARP];

    const float qt = q[(size_t)bh * DK + t];
    const float kt = k[(size_t)bh * DK + t];
    sq[t] = qt;
    sk[t] = kt;

    // partial q.k: per-warp butterfly over its 32 elements
    float p = qt * kt;
    #pragma unroll
    for (int off = 16; off > 0; off >>= 1)
        p += __shfl_xor_sync(0xFFFFFFFFu, p, off);
    if (lane == 0) wqk[warp] = p;
    __syncthreads();

    const float qk = wqk[0] + wqk[1] + wqk[2] + wqk[3];

    const float4* S = reinterpret_cast<const float4*>(state + (size_t)bh * (DK * DV));

    float4 qS = make_float4(0.f, 0.f, 0.f, 0.f);
    float4 kS = make_float4(0.f, 0.f, 0.f, 0.f);

    const int row0 = warp * 32;
    #pragma unroll 8
    for (int i = 0; i < 32; ++i) {
        const int kk = row0 + i;
        const float4 s = S[kk * (DV / 4) + lane];  // warp reads full 512B row
        const float qc = sq[kk];                   // smem broadcast
        const float kc = sk[kk];
        qS.x = fmaf(qc, s.x, qS.x);  kS.x = fmaf(kc, s.x, kS.x);
        qS.y = fmaf(qc, s.y, qS.y);  kS.y = fmaf(kc, s.y, kS.y);
        qS.z = fmaf(qc, s.z, qS.z);  kS.z = fmaf(kc, s.z, kS.z);
        qS.w = fmaf(qc, s.w, qS.w);  kS.w = fmaf(kc, s.w, kS.w);
    }

    reinterpret_cast<float4*>(&redQ[warp][0])[lane] = qS;
    reinterpret_cast<float4*>(&redK[warp][0])[lane] = kS;
    __syncthreads();

    const float qs = redQ[0][t] + redQ[1][t] + redQ[2][t] + redQ[3][t];
    const float ks = redK[0][t] + redK[1][t] + redK[2][t] + redK[3][t];

    const float g  = gate[bh];
    const float bt = beta[bh];
    const float vv = v[(size_t)bh * DV + t];

    out[(size_t)bh * DV + t] = fmaf(g, qs, (qk * bt) * (vv - g * ks));
}

extern "C" void kernel_launch(void* const* d_in, const int* in_sizes, int n_in,
                              void* d_out, int out_size) {
    const float* q     = (const float*)d_in[0];
    const float* k     = (const float*)d_in[1];
    const float* v     = (const float*)d_in[2];
    const float* beta  = (const float*)d_in[3];
    const float* gate  = (const float*)d_in[4];
    const float* state = (const float*)d_in[5];
    float* out = (float*)d_out;

    const int BH = in_sizes[3];   // beta: B*H elements

    deltanet_step_kernel<<<BH, DV>>>(q, k, v, beta, gate, state, out);
}